// round 16
// baseline (speedup 1.0000x reference)
#include <cuda_runtime.h>
#include <cuda_fp16.h>

#define NN 50000
#define EE 800000
#define SCAN_B 256
#define NBLK ((NN + SCAN_B - 1) / SCAN_B)  // 196
#define GB ((NN + 127) / 128)              // 391 gemm tiles
#define GB_A 196                           // gemm1a tiles (hosts hist)
#define GB_B (GB - GB_A)                   // gemm1b tiles (hosts scatter)

#define LDAB 136  // fp16 smem leading dim (68 words; 68 mod 32 = 4 -> conflict-free frags)
#define LDC 132   // fp32 epilogue smem leading dim (<=2-way)

// Prelude modes for the fused GEMM kernel
#define PRE_NONE 0
#define PRE_HIST 1
#define PRE_SCATTER 2

// Scratch (no allocation allowed -> __device__ globals)
__device__ __half g_hh[NN * 128];      // h (then reused for aggH), fp16
__device__ __half g_hid[NN * 128];     // hidden, fp16
__device__ int g_csr[EE];
__device__ int g_cnt[NN];              // zero-init at load; self-zeroing per call
__device__ int g_rowptr[NN + 1];
__device__ int g_cursor[NN];
__device__ float g_dinv[NN];
__device__ int g_bsum[NBLK];
__device__ int g_boff[NBLK];

// ---------------------------------------------------------------------------
__device__ __forceinline__ float4 ld4(const float* p) {
    return *(const float4*)p;
}
__device__ __forceinline__ float4 ld4(const __half* p) {
    uint2 u = *(const uint2*)p;
    __half2 h0 = *reinterpret_cast<__half2*>(&u.x);
    __half2 h1 = *reinterpret_cast<__half2*>(&u.y);
    float2 f0 = __half22float2(h0), f1 = __half22float2(h1);
    return make_float4(f0.x, f0.y, f1.x, f1.y);
}
__device__ __forceinline__ void st4(float* p, float4 v) { *(float4*)p = v; }
__device__ __forceinline__ void st4(__half* p, float4 v) {
    __half2 h0 = __floats2half2_rn(v.x, v.y);
    __half2 h1 = __floats2half2_rn(v.z, v.w);
    uint2 u;
    u.x = *reinterpret_cast<unsigned*>(&h0);
    u.y = *reinterpret_cast<unsigned*>(&h1);
    *(uint2*)p = u;
}

// m16n8k16 HMMA, fp16 inputs, fp32 accumulate (supported warp-MMA on sm_103a)
__device__ __forceinline__ void mma16816(float* c, const unsigned* a,
                                         const unsigned* b) {
    asm volatile(
        "mma.sync.aligned.m16n8k16.row.col.f32.f16.f16.f32 "
        "{%0,%1,%2,%3}, {%4,%5,%6,%7}, {%8,%9}, {%0,%1,%2,%3};"
        : "+f"(c[0]), "+f"(c[1]), "+f"(c[2]), "+f"(c[3])
        : "r"(a[0]), "r"(a[1]), "r"(a[2]), "r"(a[3]), "r"(b[0]), "r"(b[1]));
}

// Per-block edge dtype detection: int64 LE with values < 2^31 has every odd
// 32-bit word zero; random int32 ids make that astronomically unlikely.
// Reads hit L1/L2 after the first block -> effectively free.
__device__ __forceinline__ int detect_is64_block(const void* ei, int* sflag) {
    if (threadIdx.x == 0) {
        const int* w = (const int*)ei;
        int all0 = 1;
#pragma unroll 1
        for (int i = 1; i < 256; i += 2) all0 &= (w[i] == 0);
        *sflag = all0;
    }
    __syncthreads();
    return *sflag;
}

// ---------------------------------------------------------------------------
// Hierarchical exclusive scan over g_cnt (3 tiny kernels, all-SM parallel).
__global__ void bsum_kernel() {
    __shared__ int sw[8];
    int i = blockIdx.x * SCAN_B + threadIdx.x;
    int v = (i < NN) ? g_cnt[i] : 0;
#pragma unroll
    for (int o = 16; o > 0; o >>= 1) v += __shfl_down_sync(~0u, v, o);
    int lane = threadIdx.x & 31, w = threadIdx.x >> 5;
    if (lane == 0) sw[w] = v;
    __syncthreads();
    if (threadIdx.x < 8) {
        int s = sw[threadIdx.x];
#pragma unroll
        for (int o = 4; o > 0; o >>= 1) s += __shfl_down_sync(0xff, s, o);
        if (threadIdx.x == 0) g_bsum[blockIdx.x] = s;
    }
}

__global__ void boff_kernel() {
    __shared__ int sm[256];
    int tid = threadIdx.x;
    int v = (tid < NBLK) ? g_bsum[tid] : 0;
    sm[tid] = v;
    __syncthreads();
    for (int d = 1; d < 256; d <<= 1) {
        int t = (tid >= d) ? sm[tid - d] : 0;
        __syncthreads();
        sm[tid] += t;
        __syncthreads();
    }
    if (tid < NBLK) g_boff[tid] = sm[tid] - v;  // exclusive
    if (tid == 255) g_rowptr[NN] = sm[255];
}

__global__ void scanwrite_kernel() {
    __shared__ int swarp[8];
    int tid = threadIdx.x;
    int i = blockIdx.x * SCAN_B + tid;
    int c = (i < NN) ? g_cnt[i] : 0;
    int v = c;
    int lane = tid & 31, w = tid >> 5;
#pragma unroll
    for (int o = 1; o < 32; o <<= 1) {
        int t = __shfl_up_sync(~0u, v, o);
        if (lane >= o) v += t;
    }
    if (lane == 31) swarp[w] = v;
    __syncthreads();
    if (tid < 8) {
        int s = swarp[tid];
#pragma unroll
        for (int o = 1; o < 8; o <<= 1) {
            int t = __shfl_up_sync(0xff, s, o);
            if (tid >= o) s += t;
        }
        swarp[tid] = s;
    }
    __syncthreads();
    int excl = v - c + (w > 0 ? swarp[w - 1] : 0) + g_boff[blockIdx.x];
    if (i < NN) {
        g_rowptr[i] = excl;
        g_cursor[i] = excl;
        g_dinv[i] = rsqrtf((float)c + 1.0f);
        g_cnt[i] = 0;  // self-zero for the next call (we are the last reader)
    }
}

// ---------------------------------------------------------------------------
// Tensor-core GEMM via mma.sync m16n8k16 (fp16 in / fp32 accum):
// [NN,128] x [128,128]. Block = 128x128 tile (tile index = blockIdx.x +
// tile_off), 8 warps (4m x 2n), warp = 32x64 = 2x8 HMMA tiles.
// A from row-major As[row][k]; B from TRANSPOSED BsT[n][k]. Epilogue via
// smem Cs (reused space): bias / relu / split / fp16-out.
// prelude: PRE_HIST = in-degree histogram, PRE_SCATTER = CSR scatter —
// atomic-bound work that hides under the tensor-bound GEMM (thread-level
// fusion, same blocks/smem -> no occupancy penalty).
__global__ void __launch_bounds__(256, 1) gemm_tc_kernel(
    const void* __restrict__ Xv, const float* __restrict__ B0,
    const float* __restrict__ B1, const float* __restrict__ bias0,
    const float* __restrict__ bias1, void* __restrict__ O0v,
    float* __restrict__ O1, int do_relu, int in16, int out16,
    int tile_off, int prelude, const void* ei) {
    extern __shared__ char smem[];
    __half* As = (__half*)smem;           // 128 x LDAB halves
    __half* BsT = As + 128 * LDAB;        // 128 x LDAB halves (W transposed)
    float* Cs = (float*)smem;             // 128 x LDC floats (reuse)
    __shared__ int s_is64;
    int tid = threadIdx.x;

    if (prelude != PRE_NONE) {
        int is64 = detect_is64_block(ei, &s_is64);
        int stride = gridDim.x * blockDim.x;
        int start = blockIdx.x * blockDim.x + tid;
        if (prelude == PRE_HIST) {
            if (is64) {
                const long long* p = (const long long*)ei;
                for (int i = start; i < EE; i += stride)
                    atomicAdd(&g_cnt[(int)p[EE + i]], 1);
            } else {
                const int* p = (const int*)ei;
                for (int i = start; i < EE; i += stride)
                    atomicAdd(&g_cnt[p[EE + i]], 1);
            }
        } else {  // PRE_SCATTER
            if (is64) {
                const long long* p = (const long long*)ei;
                for (int i = start; i < EE; i += stride) {
                    int s = (int)p[i];
                    int d = (int)p[EE + i];
                    int pos = atomicAdd(&g_cursor[d], 1);
                    g_csr[pos] = s;
                }
            } else {
                const int* p = (const int*)ei;
                for (int i = start; i < EE; i += stride) {
                    int s = p[i];
                    int d = p[EE + i];
                    int pos = atomicAdd(&g_cursor[d], 1);
                    g_csr[pos] = s;
                }
            }
        }
    }

    int row0 = (blockIdx.x + tile_off) * 128;

    // Fill As (X tile, fp16), 4 elements per idx step
    for (int idx = tid; idx < 128 * 32; idx += 256) {
        int r = idx >> 5, c4 = idx & 31;
        int grow = row0 + r;
        float4 v;
        if (grow >= NN) {
            v = make_float4(0.f, 0.f, 0.f, 0.f);
        } else if (in16) {
            v = ld4((const __half*)Xv + (size_t)grow * 128 + c4 * 4);
        } else {
            v = ld4((const float*)Xv + (size_t)grow * 128 + c4 * 4);
        }
        st4(As + r * LDAB + c4 * 4, v);
    }
    // Fill BsT (W transposed, fp16): BsT[n][k] = W[k][n]
    for (int idx = tid; idx < 128 * 32; idx += 256) {
        int k = idx >> 5, c4 = idx & 31;
        int n = c4 * 4;
        float4 v;
        if (B1) {
            v = (n < 64) ? ld4(B0 + k * 64 + n) : ld4(B1 + k * 64 + n - 64);
        } else {
            v = ld4(B0 + k * 128 + n);
        }
        BsT[(n + 0) * LDAB + k] = __float2half_rn(v.x);
        BsT[(n + 1) * LDAB + k] = __float2half_rn(v.y);
        BsT[(n + 2) * LDAB + k] = __float2half_rn(v.z);
        BsT[(n + 3) * LDAB + k] = __float2half_rn(v.w);
    }
    __syncthreads();

    int warp = tid >> 5, lane = tid & 31;
    int wm = warp >> 1, wn = warp & 1;   // 4 x 2 warp grid
    int g = lane >> 2, tig = lane & 3;   // mma fragment coords

    float c[2][8][4];
#pragma unroll
    for (int mi = 0; mi < 2; mi++)
#pragma unroll
        for (int ni = 0; ni < 8; ni++)
#pragma unroll
            for (int q = 0; q < 4; q++) c[mi][ni][q] = 0.f;

    const unsigned* As32 = (const unsigned*)As;
    const unsigned* Bs32 = (const unsigned*)BsT;
    const int LW = LDAB >> 1;  // 68 words per row

#pragma unroll
    for (int k0 = 0; k0 < 128; k0 += 16) {
        int kw = (k0 >> 1) + tig;  // word offset of this lane's k-pair
        unsigned a[2][4], b[8][2];
#pragma unroll
        for (int mi = 0; mi < 2; mi++) {
            int r = wm * 32 + mi * 16 + g;
            int base = r * LW + kw;
            a[mi][0] = As32[base];
            a[mi][1] = As32[base + 8 * LW];
            a[mi][2] = As32[base + 4];
            a[mi][3] = As32[base + 8 * LW + 4];
        }
#pragma unroll
        for (int ni = 0; ni < 8; ni++) {
            int n = wn * 64 + ni * 8 + g;
            int base = n * LW + kw;
            b[ni][0] = Bs32[base];
            b[ni][1] = Bs32[base + 4];
        }
#pragma unroll
        for (int mi = 0; mi < 2; mi++)
#pragma unroll
            for (int ni = 0; ni < 8; ni++)
                mma16816(c[mi][ni], a[mi], b[ni]);
    }

    __syncthreads();  // all warps done reading As/BsT before Cs overwrite

#pragma unroll
    for (int mi = 0; mi < 2; mi++) {
        int r = wm * 32 + mi * 16 + g;
#pragma unroll
        for (int ni = 0; ni < 8; ni++) {
            int col = wn * 64 + ni * 8 + tig * 2;
            *(float2*)(Cs + r * LDC + col) =
                make_float2(c[mi][ni][0], c[mi][ni][1]);
            *(float2*)(Cs + (r + 8) * LDC + col) =
                make_float2(c[mi][ni][2], c[mi][ni][3]);
        }
    }
    __syncthreads();

    // Epilogue: bias / relu / dtype / split
    for (int idx = tid; idx < 128 * 32; idx += 256) {
        int r = idx >> 5, c4 = idx & 31;
        int grow = row0 + r;
        if (grow >= NN) continue;
        int col = c4 * 4;
        float4 o = *(float4*)(Cs + r * LDC + col);
        if (bias0) {
            float4 bi;
            if (B1)
                bi = (col < 64) ? *(const float4*)(bias0 + col)
                                : *(const float4*)(bias1 + col - 64);
            else
                bi = *(const float4*)(bias0 + col);
            o.x += bi.x; o.y += bi.y; o.z += bi.z; o.w += bi.w;
        }
        if (do_relu) {
            o.x = fmaxf(o.x, 0.f); o.y = fmaxf(o.y, 0.f);
            o.z = fmaxf(o.z, 0.f); o.w = fmaxf(o.w, 0.f);
        }
        if (B1) {
            float* O0 = (float*)O0v;
            if (col < 64)
                *(float4*)(O0 + (size_t)grow * 64 + col) = o;
            else
                *(float4*)(O1 + (size_t)grow * 64 + col - 64) = o;
        } else if (out16) {
            st4((__half*)O0v + (size_t)grow * 128 + col, o);
        } else {
            st4((float*)O0v + (size_t)grow * 128 + col, o);
        }
    }
}

// ---------------------------------------------------------------------------
// Aggregation (R5-proven loop shape — ptxas unrolls the gather for MLP).
// OUT[c] = dinv[c]*(sum_{r in in(c)} dinv[r]*H[r]) + dinv[c]^2*H[c]
template <typename TIN, typename TOUT>
__global__ void agg_kernel(const TIN* __restrict__ H, TOUT* __restrict__ OUT,
                           const float* __restrict__ bias, int do_relu) {
    int gw = (blockIdx.x * blockDim.x + threadIdx.x) >> 5;
    if (gw >= NN) return;
    int lane = threadIdx.x & 31;
    int node = gw;
    int s = g_rowptr[node], e = g_rowptr[node + 1];
    float ax = 0.f, ay = 0.f, az = 0.f, aw = 0.f;
    for (int j = s; j < e; j++) {
        int src = g_csr[j];
        float wgt = g_dinv[src];
        float4 v = ld4(H + (size_t)src * 128 + lane * 4);
        ax += wgt * v.x; ay += wgt * v.y; az += wgt * v.z; aw += wgt * v.w;
    }
    float dc = g_dinv[node];
    float dc2 = dc * dc;
    float4 sv = ld4(H + (size_t)node * 128 + lane * 4);
    ax = dc * ax + dc2 * sv.x;
    ay = dc * ay + dc2 * sv.y;
    az = dc * az + dc2 * sv.z;
    aw = dc * aw + dc2 * sv.w;
    if (bias) {
        float4 bi = *(const float4*)(bias + lane * 4);
        ax += bi.x; ay += bi.y; az += bi.z; aw += bi.w;
    }
    if (do_relu) {
        ax = fmaxf(ax, 0.f); ay = fmaxf(ay, 0.f);
        az = fmaxf(az, 0.f); aw = fmaxf(aw, 0.f);
    }
    st4(OUT + (size_t)node * 128 + lane * 4, make_float4(ax, ay, az, aw));
}

// ---------------------------------------------------------------------------
extern "C" void kernel_launch(void* const* d_in, const int* in_sizes, int n_in,
                              void* d_out, int out_size) {
    const float* x = (const float*)d_in[0];
    const void* ei = d_in[1];
    const float* W1 = (const float*)d_in[2];
    const float* b1 = (const float*)d_in[3];
    const float* W2 = (const float*)d_in[4];
    const float* b2 = (const float*)d_in[5];
    const float* W3 = (const float*)d_in[6];
    const float* b3 = (const float*)d_in[7];
    float* out = (float*)d_out;

    __half* phh;
    __half* phid;
    cudaGetSymbolAddress((void**)&phh, g_hh);
    cudaGetSymbolAddress((void**)&phid, g_hid);

    const size_t smem = 2 * 128 * LDAB * sizeof(__half);  // 69632 B
    cudaFuncSetAttribute(gemm_tc_kernel,
                         cudaFuncAttributeMaxDynamicSharedMemorySize,
                         (int)smem);

    int ablocks = (NN * 32 + 255) / 256;

    // gemm1a: tiles [0,196) of h = x @ W1 -> fp16, hosting the in-degree
    // histogram (atomic-bound, hides under tensor-bound GEMM)
    gemm_tc_kernel<<<GB_A, 256, smem>>>(x, W1, nullptr, nullptr, nullptr,
                                        phh, nullptr, 0, 0, 1,
                                        0, PRE_HIST, ei);
    // exclusive scan of degrees -> rowptr/cursor/dinv (only exposed prefix)
    bsum_kernel<<<NBLK, SCAN_B>>>();
    boff_kernel<<<1, 256>>>();
    scanwrite_kernel<<<NBLK, SCAN_B>>>();
    // gemm1b: tiles [196,391), hosting the CSR scatter (needs cursors)
    gemm_tc_kernel<<<GB_B, 256, smem>>>(x, W1, nullptr, nullptr, nullptr,
                                        phh, nullptr, 0, 0, 1,
                                        GB_A, PRE_SCATTER, ei);
    // hidden = relu(A h + b1) -> fp16
    agg_kernel<__half, __half><<<ablocks, 256>>>(phh, phid, b1, 1);
    // aggH = A hidden -> fp16 (reuses g_hh; h is dead after agg1)
    agg_kernel<__half, __half><<<ablocks, 256>>>(phid, phh, nullptr, 0);
    // x1 = relu(aggH @ W2 + b2), x2 = relu(aggH @ W3 + b3)  (tensor cores)
    gemm_tc_kernel<<<GB, 256, smem>>>(phh, W2, W3, b2, b3, out,
                                      out + (size_t)NN * 64, 1, 1, 0,
                                      0, PRE_NONE, nullptr);
}